// round 1
// baseline (speedup 1.0000x reference)
#include <cuda_runtime.h>
#include <cuda_bf16.h>
#include <math.h>

// ---------------- problem constants ----------------
#define BB 512
#define DD 128
#define NL 16
#define LAYERS 4
#define NHEAD 4
#define HDIM 32
#define NDRUG 25600
#define NENZ 153600
#define CAP_D 128
#define CAP_E 512

// ---------------- scratch (device globals; no allocs allowed) ----------------
constexpr size_t SZ_KPD = (size_t)NDRUG * DD;        // 3,276,800
constexpr size_t SZ_KPE = (size_t)NENZ * DD;         // 19,660,800
constexpr size_t SZ_LAT = (size_t)BB * NL * DD;      // 1,048,576
constexpr size_t SZ_H1  = (size_t)BB * NL * 2 * DD;  // 2,097,152
constexpr size_t SZ_HH  = (size_t)BB * DD;           // 65,536

constexpr size_t OFF_KPD = 0;
constexpr size_t OFF_VPD = OFF_KPD + SZ_KPD;
constexpr size_t OFF_KPE = OFF_VPD + SZ_KPD;
constexpr size_t OFF_VPE = OFF_KPE + SZ_KPE;
constexpr size_t OFF_LAT = OFF_VPE + SZ_KPE;
constexpr size_t OFF_NL  = OFF_LAT + SZ_LAT;
constexpr size_t OFF_TMP = OFF_NL  + SZ_LAT;
constexpr size_t OFF_QH  = OFF_TMP + SZ_LAT;
constexpr size_t OFF_O   = OFF_QH  + SZ_LAT;
constexpr size_t OFF_H1  = OFF_O   + SZ_LAT;
constexpr size_t OFF_HH  = OFF_H1  + SZ_H1;
constexpr size_t SCRATCH_FLOATS = OFF_HH + SZ_HH;    // ~53.3M floats ~213 MB

__device__ float g_scratch[SCRATCH_FLOATS];
__device__ int   g_starts[2 * (BB + 1)];             // [0..512] drug, [513..1025] enzyme

// ---------------- starts via binary search (batch arrays are sorted) ----------------
__global__ void starts_kernel(const int* __restrict__ batch, int n, int* __restrict__ starts) {
    int b = threadIdx.x;  // 0..511
    int lo = 0, hi = n;
    while (lo < hi) {
        int mid = (lo + hi) >> 1;
        if (batch[mid] < b) lo = mid + 1; else hi = mid;
    }
    starts[b] = lo;
    if (b == 0) starts[BB] = n;
}

// ---------------- latent broadcast ----------------
__global__ void init_lat_kernel(const float* __restrict__ latents, float* __restrict__ lat) {
    int idx = blockIdx.x * blockDim.x + threadIdx.x;   // < 512*2048
    lat[idx] = latents[idx & (NL * DD - 1)];           // 2048 = pow2
}

// ---------------- layernorm: one row (128) per block ----------------
__global__ void ln_kernel(const float* __restrict__ x, const float* __restrict__ g,
                          const float* __restrict__ b, float* __restrict__ y) {
    int row = blockIdx.x;
    int tid = threadIdx.x;  // 128
    float v = x[(size_t)row * DD + tid];
    float s = v;
    #pragma unroll
    for (int o = 16; o > 0; o >>= 1) s += __shfl_xor_sync(0xffffffffu, s, o);
    __shared__ float red[4];
    if ((tid & 31) == 0) red[tid >> 5] = s;
    __syncthreads();
    float mean = (red[0] + red[1] + red[2] + red[3]) * (1.0f / DD);
    float d = v - mean;
    float q = d * d;
    #pragma unroll
    for (int o = 16; o > 0; o >>= 1) q += __shfl_xor_sync(0xffffffffu, q, o);
    __shared__ float red2[4];
    if ((tid & 31) == 0) red2[tid >> 5] = q;
    __syncthreads();
    float var = (red2[0] + red2[1] + red2[2] + red2[3]) * (1.0f / DD);
    y[(size_t)row * DD + tid] = d * rsqrtf(var + 1e-5f) * g[tid] + b[tid];
}

// ---------------- generic fp32 GEMM: C[M,N] = act(A[M,K] @ W[N,K]^T + bias) (+= C) ----
// flags: bit0 = relu, bit1 = accumulate into C
// Requires: M % 64 == 0, N % 64 == 0, K % 16 == 0, 16B-aligned pointers.
__global__ __launch_bounds__(256) void gemm_kernel(
    const float* __restrict__ A, const float* __restrict__ W,
    const float* __restrict__ bias, float* __restrict__ C,
    int M, int K, int N, int flags)
{
    __shared__ float As[16][68];
    __shared__ float Ws[16][68];
    int m0 = blockIdx.y * 64;
    int n0 = blockIdx.x * 64;
    int tid = threadIdx.x;
    int lr = tid >> 2;          // 0..63
    int lc = (tid & 3) * 4;     // 0,4,8,12
    int ty = tid >> 4;          // 0..15 -> rows
    int tx = tid & 15;          // 0..15 -> cols

    float acc[4][4] = {};
    const float* Ap = A + (size_t)(m0 + lr) * K + lc;
    const float* Wp = W + (size_t)(n0 + lr) * K + lc;

    for (int k0 = 0; k0 < K; k0 += 16) {
        float4 a = *(const float4*)(Ap + k0);
        float4 w = *(const float4*)(Wp + k0);
        __syncthreads();
        As[lc + 0][lr] = a.x; As[lc + 1][lr] = a.y; As[lc + 2][lr] = a.z; As[lc + 3][lr] = a.w;
        Ws[lc + 0][lr] = w.x; Ws[lc + 1][lr] = w.y; Ws[lc + 2][lr] = w.z; Ws[lc + 3][lr] = w.w;
        __syncthreads();
        #pragma unroll
        for (int k = 0; k < 16; k++) {
            float4 av = *(const float4*)&As[k][ty * 4];
            float4 wv = *(const float4*)&Ws[k][tx * 4];
            float aa[4] = {av.x, av.y, av.z, av.w};
            float ww[4] = {wv.x, wv.y, wv.z, wv.w};
            #pragma unroll
            for (int i = 0; i < 4; i++)
                #pragma unroll
                for (int j = 0; j < 4; j++)
                    acc[i][j] += aa[i] * ww[j];
        }
    }

    float bcol[4];
    #pragma unroll
    for (int j = 0; j < 4; j++) bcol[j] = bias[n0 + tx * 4 + j];

    #pragma unroll
    for (int i = 0; i < 4; i++) {
        int m = m0 + ty * 4 + i;
        float4 c;
        c.x = acc[i][0] + bcol[0];
        c.y = acc[i][1] + bcol[1];
        c.z = acc[i][2] + bcol[2];
        c.w = acc[i][3] + bcol[3];
        if (flags & 1) {
            c.x = fmaxf(c.x, 0.f); c.y = fmaxf(c.y, 0.f);
            c.z = fmaxf(c.z, 0.f); c.w = fmaxf(c.w, 0.f);
        }
        float* p = C + (size_t)m * N + n0 + tx * 4;
        if (flags & 2) {
            float4 o = *(const float4*)p;
            c.x += o.x; c.y += o.y; c.z += o.z; c.w += o.w;
        }
        *(float4*)p = c;
    }
}

// ---------------- attention: one block per (batch, head), 128 threads ----------------
// qh: [B*16,128] (col = h*32+d); kp/vp: [Ntok,128] projected tokens (sorted by batch)
__global__ void attn_kernel(const float* __restrict__ qh, const float* __restrict__ kp,
                            const float* __restrict__ vp, const int* __restrict__ starts,
                            const float* __restrict__ bv, float* __restrict__ o, int cap)
{
    int b = blockIdx.x, h = blockIdx.y;
    int tid = threadIdx.x;
    int t0 = starts[b];
    int cnt = starts[b + 1] - t0;
    if (cnt > cap) cnt = cap;  // matches reference scatter-drop semantics

    extern __shared__ float sm[];
    float* sq = sm;           // 16*32
    float* ss = sm + 512;     // 16*cap

    for (int i = tid; i < 512; i += 128) {
        int q = i >> 5, d = i & 31;
        sq[i] = qh[((size_t)(b * NL + q)) * DD + h * HDIM + d];
    }
    __syncthreads();

    int d  = tid & 31;
    int qg = tid >> 5;  // 0..3

    if (cnt == 0) {
        // all keys masked in reference -> uniform softmax over zero-rows -> o = bv
        float v = bv[h * HDIM + d];
        #pragma unroll
        for (int i = 0; i < 4; i++)
            o[((size_t)(b * NL + qg * 4 + i)) * DD + h * HDIM + d] = v;
        return;
    }

    // scores: thread-per-key
    for (int kk = tid; kk < cnt; kk += 128) {
        const float* kr = kp + ((size_t)(t0 + kk)) * DD + h * HDIM;
        float kvv[32];
        #pragma unroll
        for (int j = 0; j < 8; j++) {
            float4 t = *(const float4*)(kr + j * 4);
            kvv[j * 4] = t.x; kvv[j * 4 + 1] = t.y; kvv[j * 4 + 2] = t.z; kvv[j * 4 + 3] = t.w;
        }
        #pragma unroll
        for (int q = 0; q < 16; q++) {
            float acc = 0.f;
            #pragma unroll
            for (int j = 0; j < 32; j++) acc += sq[q * 32 + j] * kvv[j];
            ss[q * cap + kk] = acc * 0.17677669529663689f;  // 1/sqrt(32)
        }
    }
    __syncthreads();

    // softmax: warp w handles rows w, w+4, w+8, w+12
    int warp = tid >> 5, lane = tid & 31;
    for (int q = warp; q < 16; q += 4) {
        float m = -1e30f;
        for (int kk = lane; kk < cnt; kk += 32) m = fmaxf(m, ss[q * cap + kk]);
        #pragma unroll
        for (int off = 16; off > 0; off >>= 1) m = fmaxf(m, __shfl_xor_sync(0xffffffffu, m, off));
        float s = 0.f;
        for (int kk = lane; kk < cnt; kk += 32) {
            float e = expf(ss[q * cap + kk] - m);
            ss[q * cap + kk] = e;
            s += e;
        }
        #pragma unroll
        for (int off = 16; off > 0; off >>= 1) s += __shfl_xor_sync(0xffffffffu, s, off);
        float inv = 1.0f / s;
        for (int kk = lane; kk < cnt; kk += 32) ss[q * cap + kk] *= inv;
    }
    __syncthreads();

    // o = probs @ V: lane d, each thread accumulates 4 q-rows; coalesced V reads
    float acc[4] = {0.f, 0.f, 0.f, 0.f};
    #pragma unroll 4
    for (int kk = 0; kk < cnt; kk++) {
        float v = vp[((size_t)(t0 + kk)) * DD + h * HDIM + d];
        #pragma unroll
        for (int i = 0; i < 4; i++) acc[i] += ss[(qg * 4 + i) * cap + kk] * v;
    }
    #pragma unroll
    for (int i = 0; i < 4; i++)
        o[((size_t)(b * NL + qg * 4 + i)) * DD + h * HDIM + d] = acc[i];
}

// ---------------- head stage 2: out[b] = softplus(dot(h[b], w2) + b2) ----------------
__global__ void head2_kernel(const float* __restrict__ hbuf, const float* __restrict__ w2,
                             const float* __restrict__ b2, float* __restrict__ out)
{
    int b = blockIdx.x, tid = threadIdx.x;  // 128
    float v = hbuf[(size_t)b * DD + tid] * w2[tid];
    #pragma unroll
    for (int o = 16; o > 0; o >>= 1) v += __shfl_xor_sync(0xffffffffu, v, o);
    __shared__ float red[4];
    if ((tid & 31) == 0) red[tid >> 5] = v;
    __syncthreads();
    if (tid == 0) {
        float x = red[0] + red[1] + red[2] + red[3] + b2[0];
        out[b] = (x > 20.f) ? x : log1pf(expf(x));
    }
}

// ---------------- host-side launcher ----------------
static inline void run_gemm(const float* A, const float* W, const float* bias, float* C,
                            int M, int K, int N, int flags) {
    dim3 grid(N / 64, M / 64);
    gemm_kernel<<<grid, 256>>>(A, W, bias, C, M, K, N, flags);
}

extern "C" void kernel_launch(void* const* d_in, const int* in_sizes, int n_in,
                              void* d_out, int out_size) {
    const float* drug_k    = (const float*)d_in[0];
    const float* drug_v    = (const float*)d_in[1];
    const float* enzyme_k  = (const float*)d_in[2];
    const float* enzyme_v  = (const float*)d_in[3];
    const int*   drug_batch   = (const int*)d_in[4];
    const int*   enzyme_batch = (const int*)d_in[5];
    const float* latents   = (const float*)d_in[6];
    const float* wq_d      = (const float*)d_in[7];
    const float* bq_d      = (const float*)d_in[8];
    const float* wq_e      = (const float*)d_in[9];
    const float* bq_e      = (const float*)d_in[10];
    const float* mha_d_w   = (const float*)d_in[11];
    const float* mha_d_b   = (const float*)d_in[12];
    const float* mha_d_ow  = (const float*)d_in[13];
    const float* mha_d_ob  = (const float*)d_in[14];
    const float* mha_e_w   = (const float*)d_in[15];
    const float* mha_e_b   = (const float*)d_in[16];
    const float* mha_e_ow  = (const float*)d_in[17];
    const float* mha_e_ob  = (const float*)d_in[18];
    const float* ln1_g     = (const float*)d_in[19];
    const float* ln1_b     = (const float*)d_in[20];
    const float* ln2_g     = (const float*)d_in[21];
    const float* ln2_b     = (const float*)d_in[22];
    const float* ffn_w1    = (const float*)d_in[23];
    const float* ffn_b1    = (const float*)d_in[24];
    const float* ffn_w2    = (const float*)d_in[25];
    const float* ffn_b2    = (const float*)d_in[26];
    const float* head_w1   = (const float*)d_in[27];
    const float* head_b1   = (const float*)d_in[28];
    const float* head_w2   = (const float*)d_in[29];
    const float* head_b2   = (const float*)d_in[30];

    float* scratch; cudaGetSymbolAddress((void**)&scratch, g_scratch);
    int* startsbuf; cudaGetSymbolAddress((void**)&startsbuf, g_starts);

    float* kpd = scratch + OFF_KPD;
    float* vpd = scratch + OFF_VPD;
    float* kpe = scratch + OFF_KPE;
    float* vpe = scratch + OFF_VPE;
    float* lat = scratch + OFF_LAT;
    float* nl  = scratch + OFF_NL;
    float* tmp = scratch + OFF_TMP;
    float* qh  = scratch + OFF_QH;
    float* ob  = scratch + OFF_O;
    float* h1  = scratch + OFF_H1;
    float* hh  = scratch + OFF_HH;
    int* starts_d = startsbuf;
    int* starts_e = startsbuf + (BB + 1);

    starts_kernel<<<1, BB>>>(drug_batch, NDRUG, starts_d);
    starts_kernel<<<1, BB>>>(enzyme_batch, NENZ, starts_e);
    init_lat_kernel<<<(BB * NL * DD) / 256, 256>>>(latents, lat);

    const int MROW = BB * NL;  // 8192

    for (int l = 0; l < LAYERS; l++) {
        const float* Wd = mha_d_w + (size_t)l * 3 * DD * DD;
        const float* Bd = mha_d_b + (size_t)l * 3 * DD;
        const float* We = mha_e_w + (size_t)l * 3 * DD * DD;
        const float* Be = mha_e_b + (size_t)l * 3 * DD;

        ln_kernel<<<MROW, DD>>>(lat, ln1_g + l * DD, ln1_b + l * DD, nl);

        // --- drug branch ---
        run_gemm(nl, wq_d + (size_t)l * DD * DD, bq_d + l * DD, tmp, MROW, DD, DD, 0);
        run_gemm(tmp, Wd, Bd, qh, MROW, DD, DD, 0);
        run_gemm(drug_k, Wd + DD * DD,     Bd + DD,     kpd, NDRUG, DD, DD, 0);
        run_gemm(drug_v, Wd + 2 * DD * DD, Bd + 2 * DD, vpd, NDRUG, DD, DD, 0);
        attn_kernel<<<dim3(BB, NHEAD), 128, (512 + 16 * CAP_D) * sizeof(float)>>>(
            qh, kpd, vpd, starts_d, Bd + 2 * DD, ob, CAP_D);
        run_gemm(ob, mha_d_ow + (size_t)l * DD * DD, mha_d_ob + l * DD, lat, MROW, DD, DD, 2);

        // --- enzyme branch ---
        run_gemm(nl, wq_e + (size_t)l * DD * DD, bq_e + l * DD, tmp, MROW, DD, DD, 0);
        run_gemm(tmp, We, Be, qh, MROW, DD, DD, 0);
        run_gemm(enzyme_k, We + DD * DD,     Be + DD,     kpe, NENZ, DD, DD, 0);
        run_gemm(enzyme_v, We + 2 * DD * DD, Be + 2 * DD, vpe, NENZ, DD, DD, 0);
        attn_kernel<<<dim3(BB, NHEAD), 128, (512 + 16 * CAP_E) * sizeof(float)>>>(
            qh, kpe, vpe, starts_e, Be + 2 * DD, ob, CAP_E);
        run_gemm(ob, mha_e_ow + (size_t)l * DD * DD, mha_e_ob + l * DD, lat, MROW, DD, DD, 2);

        // --- FFN ---
        ln_kernel<<<MROW, DD>>>(lat, ln2_g + l * DD, ln2_b + l * DD, nl);
        run_gemm(nl, ffn_w1 + (size_t)l * 2 * DD * DD, ffn_b1 + l * 2 * DD, h1, MROW, DD, 2 * DD, 1);
        run_gemm(h1, ffn_w2 + (size_t)l * DD * 2 * DD, ffn_b2 + l * DD, lat, MROW, 2 * DD, DD, 2);
    }

    // head: lat viewed as [512, 2048]
    run_gemm(lat, head_w1, head_b1, hh, BB, NL * DD, DD, 1);
    head2_kernel<<<BB, DD>>>(hh, head_w2, head_b2, (float*)d_out);
}

// round 3
// speedup vs baseline: 1.0006x; 1.0006x over previous
#include <cuda_runtime.h>
#include <cuda_bf16.h>
#include <math.h>

// ---------------- problem constants ----------------
#define BB 512
#define DD 128
#define NL 16
#define LAYERS 4
#define NHEAD 4
#define HDIM 32
#define NDRUG 25600
#define NENZ 153600
#define CAP_D 128
#define CAP_E 512

// ---------------- scratch (device globals; no allocs allowed) ----------------
constexpr size_t SZ_KPD = (size_t)NDRUG * DD;        // 3,276,800
constexpr size_t SZ_KPE = (size_t)NENZ * DD;         // 19,660,800
constexpr size_t SZ_LAT = (size_t)BB * NL * DD;      // 1,048,576
constexpr size_t SZ_H1  = (size_t)BB * NL * 2 * DD;  // 2,097,152
constexpr size_t SZ_HH  = (size_t)BB * DD;           // 65,536

constexpr size_t OFF_KPD = 0;
constexpr size_t OFF_VPD = OFF_KPD + SZ_KPD;
constexpr size_t OFF_KPE = OFF_VPD + SZ_KPD;
constexpr size_t OFF_VPE = OFF_KPE + SZ_KPE;
constexpr size_t OFF_LAT = OFF_VPE + SZ_KPE;
constexpr size_t OFF_NL  = OFF_LAT + SZ_LAT;
constexpr size_t OFF_TMP = OFF_NL  + SZ_LAT;
constexpr size_t OFF_QH  = OFF_TMP + SZ_LAT;
constexpr size_t OFF_O   = OFF_QH  + SZ_LAT;
constexpr size_t OFF_H1  = OFF_O   + SZ_LAT;
constexpr size_t OFF_HH  = OFF_H1  + SZ_H1;
constexpr size_t SCRATCH_FLOATS = OFF_HH + SZ_HH;    // ~53.3M floats ~213 MB

__device__ float g_scratch[SCRATCH_FLOATS];
__device__ int   g_starts[2 * (BB + 1)];             // [0..512] drug, [513..1025] enzyme

// ---------------- starts via binary search (batch arrays are sorted) ----------------
__global__ void starts_kernel(const int* __restrict__ batch, int n, int* __restrict__ starts) {
    int b = threadIdx.x;  // 0..511
    int lo = 0, hi = n;
    while (lo < hi) {
        int mid = (lo + hi) >> 1;
        if (batch[mid] < b) lo = mid + 1; else hi = mid;
    }
    starts[b] = lo;
    if (b == 0) starts[BB] = n;
}

// ---------------- latent broadcast ----------------
__global__ void init_lat_kernel(const float* __restrict__ latents, float* __restrict__ lat) {
    int idx = blockIdx.x * blockDim.x + threadIdx.x;   // < 512*2048
    lat[idx] = latents[idx & (NL * DD - 1)];           // 2048 = pow2
}

// ---------------- layernorm: one row (128) per block ----------------
__global__ void ln_kernel(const float* __restrict__ x, const float* __restrict__ g,
                          const float* __restrict__ b, float* __restrict__ y) {
    int row = blockIdx.x;
    int tid = threadIdx.x;  // 128
    float v = x[(size_t)row * DD + tid];
    float s = v;
    #pragma unroll
    for (int o = 16; o > 0; o >>= 1) s += __shfl_xor_sync(0xffffffffu, s, o);
    __shared__ float red[4];
    if ((tid & 31) == 0) red[tid >> 5] = s;
    __syncthreads();
    float mean = (red[0] + red[1] + red[2] + red[3]) * (1.0f / DD);
    float d = v - mean;
    float q = d * d;
    #pragma unroll
    for (int o = 16; o > 0; o >>= 1) q += __shfl_xor_sync(0xffffffffu, q, o);
    __shared__ float red2[4];
    if ((tid & 31) == 0) red2[tid >> 5] = q;
    __syncthreads();
    float var = (red2[0] + red2[1] + red2[2] + red2[3]) * (1.0f / DD);
    y[(size_t)row * DD + tid] = d * rsqrtf(var + 1e-5f) * g[tid] + b[tid];
}

// ---------------- generic fp32 GEMM: C[M,N] = act(A[M,K] @ W[N,K]^T + bias) (+= C) ----
// flags: bit0 = relu, bit1 = accumulate into C
// Requires: M % 64 == 0, N % 64 == 0, K % 16 == 0, 16B-aligned pointers.
__global__ __launch_bounds__(256) void gemm_kernel(
    const float* __restrict__ A, const float* __restrict__ W,
    const float* __restrict__ bias, float* __restrict__ C,
    int M, int K, int N, int flags)
{
    __shared__ float As[16][68];
    __shared__ float Ws[16][68];
    int m0 = blockIdx.y * 64;
    int n0 = blockIdx.x * 64;
    int tid = threadIdx.x;
    int lr = tid >> 2;          // 0..63
    int lc = (tid & 3) * 4;     // 0,4,8,12
    int ty = tid >> 4;          // 0..15 -> rows
    int tx = tid & 15;          // 0..15 -> cols

    float acc[4][4] = {};
    const float* Ap = A + (size_t)(m0 + lr) * K + lc;
    const float* Wp = W + (size_t)(n0 + lr) * K + lc;

    for (int k0 = 0; k0 < K; k0 += 16) {
        float4 a = *(const float4*)(Ap + k0);
        float4 w = *(const float4*)(Wp + k0);
        __syncthreads();
        As[lc + 0][lr] = a.x; As[lc + 1][lr] = a.y; As[lc + 2][lr] = a.z; As[lc + 3][lr] = a.w;
        Ws[lc + 0][lr] = w.x; Ws[lc + 1][lr] = w.y; Ws[lc + 2][lr] = w.z; Ws[lc + 3][lr] = w.w;
        __syncthreads();
        #pragma unroll
        for (int k = 0; k < 16; k++) {
            float4 av = *(const float4*)&As[k][ty * 4];
            float4 wv = *(const float4*)&Ws[k][tx * 4];
            float aa[4] = {av.x, av.y, av.z, av.w};
            float ww[4] = {wv.x, wv.y, wv.z, wv.w};
            #pragma unroll
            for (int i = 0; i < 4; i++)
                #pragma unroll
                for (int j = 0; j < 4; j++)
                    acc[i][j] += aa[i] * ww[j];
        }
    }

    float bcol[4];
    #pragma unroll
    for (int j = 0; j < 4; j++) bcol[j] = bias[n0 + tx * 4 + j];

    #pragma unroll
    for (int i = 0; i < 4; i++) {
        int m = m0 + ty * 4 + i;
        float4 c;
        c.x = acc[i][0] + bcol[0];
        c.y = acc[i][1] + bcol[1];
        c.z = acc[i][2] + bcol[2];
        c.w = acc[i][3] + bcol[3];
        if (flags & 1) {
            c.x = fmaxf(c.x, 0.f); c.y = fmaxf(c.y, 0.f);
            c.z = fmaxf(c.z, 0.f); c.w = fmaxf(c.w, 0.f);
        }
        float* p = C + (size_t)m * N + n0 + tx * 4;
        if (flags & 2) {
            float4 o = *(const float4*)p;
            c.x += o.x; c.y += o.y; c.z += o.z; c.w += o.w;
        }
        *(float4*)p = c;
    }
}

// ---------------- attention: one block per (batch, head), 128 threads ----------------
// qh: [B*16,128] (col = h*32+d); kp/vp: [Ntok,128] projected tokens (sorted by batch)
__global__ void attn_kernel(const float* __restrict__ qh, const float* __restrict__ kp,
                            const float* __restrict__ vp, const int* __restrict__ starts,
                            const float* __restrict__ bv, float* __restrict__ o, int cap)
{
    int b = blockIdx.x, h = blockIdx.y;
    int tid = threadIdx.x;
    int t0 = starts[b];
    int cnt = starts[b + 1] - t0;
    if (cnt > cap) cnt = cap;  // matches reference scatter-drop semantics

    extern __shared__ float sm[];
    float* sq = sm;           // 16*32
    float* ss = sm + 512;     // 16*cap

    for (int i = tid; i < 512; i += 128) {
        int q = i >> 5, d = i & 31;
        sq[i] = qh[((size_t)(b * NL + q)) * DD + h * HDIM + d];
    }
    __syncthreads();

    int d  = tid & 31;
    int qg = tid >> 5;  // 0..3

    if (cnt == 0) {
        // all keys masked in reference -> uniform softmax over zero-rows -> o = bv
        float v = bv[h * HDIM + d];
        #pragma unroll
        for (int i = 0; i < 4; i++)
            o[((size_t)(b * NL + qg * 4 + i)) * DD + h * HDIM + d] = v;
        return;
    }

    // scores: thread-per-key
    for (int kk = tid; kk < cnt; kk += 128) {
        const float* kr = kp + ((size_t)(t0 + kk)) * DD + h * HDIM;
        float kvv[32];
        #pragma unroll
        for (int j = 0; j < 8; j++) {
            float4 t = *(const float4*)(kr + j * 4);
            kvv[j * 4] = t.x; kvv[j * 4 + 1] = t.y; kvv[j * 4 + 2] = t.z; kvv[j * 4 + 3] = t.w;
        }
        #pragma unroll
        for (int q = 0; q < 16; q++) {
            float acc = 0.f;
            #pragma unroll
            for (int j = 0; j < 32; j++) acc += sq[q * 32 + j] * kvv[j];
            ss[q * cap + kk] = acc * 0.17677669529663689f;  // 1/sqrt(32)
        }
    }
    __syncthreads();

    // softmax: warp w handles rows w, w+4, w+8, w+12
    int warp = tid >> 5, lane = tid & 31;
    for (int q = warp; q < 16; q += 4) {
        float m = -1e30f;
        for (int kk = lane; kk < cnt; kk += 32) m = fmaxf(m, ss[q * cap + kk]);
        #pragma unroll
        for (int off = 16; off > 0; off >>= 1) m = fmaxf(m, __shfl_xor_sync(0xffffffffu, m, off));
        float s = 0.f;
        for (int kk = lane; kk < cnt; kk += 32) {
            float e = expf(ss[q * cap + kk] - m);
            ss[q * cap + kk] = e;
            s += e;
        }
        #pragma unroll
        for (int off = 16; off > 0; off >>= 1) s += __shfl_xor_sync(0xffffffffu, s, off);
        float inv = 1.0f / s;
        for (int kk = lane; kk < cnt; kk += 32) ss[q * cap + kk] *= inv;
    }
    __syncthreads();

    // o = probs @ V: lane d, each thread accumulates 4 q-rows; coalesced V reads
    float acc[4] = {0.f, 0.f, 0.f, 0.f};
    #pragma unroll 4
    for (int kk = 0; kk < cnt; kk++) {
        float v = vp[((size_t)(t0 + kk)) * DD + h * HDIM + d];
        #pragma unroll
        for (int i = 0; i < 4; i++) acc[i] += ss[(qg * 4 + i) * cap + kk] * v;
    }
    #pragma unroll
    for (int i = 0; i < 4; i++)
        o[((size_t)(b * NL + qg * 4 + i)) * DD + h * HDIM + d] = acc[i];
}

// ---------------- head stage 2: out[b] = softplus(dot(h[b], w2) + b2) ----------------
__global__ void head2_kernel(const float* __restrict__ hbuf, const float* __restrict__ w2,
                             const float* __restrict__ b2, float* __restrict__ out)
{
    int b = blockIdx.x, tid = threadIdx.x;  // 128
    float v = hbuf[(size_t)b * DD + tid] * w2[tid];
    #pragma unroll
    for (int o = 16; o > 0; o >>= 1) v += __shfl_xor_sync(0xffffffffu, v, o);
    __shared__ float red[4];
    if ((tid & 31) == 0) red[tid >> 5] = v;
    __syncthreads();
    if (tid == 0) {
        float x = red[0] + red[1] + red[2] + red[3] + b2[0];
        out[b] = (x > 20.f) ? x : log1pf(expf(x));
    }
}

// ---------------- host-side launcher ----------------
static inline void run_gemm(const float* A, const float* W, const float* bias, float* C,
                            int M, int K, int N, int flags) {
    dim3 grid(N / 64, M / 64);
    gemm_kernel<<<grid, 256>>>(A, W, bias, C, M, K, N, flags);
}

extern "C" void kernel_launch(void* const* d_in, const int* in_sizes, int n_in,
                              void* d_out, int out_size) {
    const float* drug_k    = (const float*)d_in[0];
    const float* drug_v    = (const float*)d_in[1];
    const float* enzyme_k  = (const float*)d_in[2];
    const float* enzyme_v  = (const float*)d_in[3];
    const int*   drug_batch   = (const int*)d_in[4];
    const int*   enzyme_batch = (const int*)d_in[5];
    const float* latents   = (const float*)d_in[6];
    const float* wq_d      = (const float*)d_in[7];
    const float* bq_d      = (const float*)d_in[8];
    const float* wq_e      = (const float*)d_in[9];
    const float* bq_e      = (const float*)d_in[10];
    const float* mha_d_w   = (const float*)d_in[11];
    const float* mha_d_b   = (const float*)d_in[12];
    const float* mha_d_ow  = (const float*)d_in[13];
    const float* mha_d_ob  = (const float*)d_in[14];
    const float* mha_e_w   = (const float*)d_in[15];
    const float* mha_e_b   = (const float*)d_in[16];
    const float* mha_e_ow  = (const float*)d_in[17];
    const float* mha_e_ob  = (const float*)d_in[18];
    const float* ln1_g     = (const float*)d_in[19];
    const float* ln1_b     = (const float*)d_in[20];
    const float* ln2_g     = (const float*)d_in[21];
    const float* ln2_b     = (const float*)d_in[22];
    const float* ffn_w1    = (const float*)d_in[23];
    const float* ffn_b1    = (const float*)d_in[24];
    const float* ffn_w2    = (const float*)d_in[25];
    const float* ffn_b2    = (const float*)d_in[26];
    const float* head_w1   = (const float*)d_in[27];
    const float* head_b1   = (const float*)d_in[28];
    const float* head_w2   = (const float*)d_in[29];
    const float* head_b2   = (const float*)d_in[30];

    float* scratch; cudaGetSymbolAddress((void**)&scratch, g_scratch);
    int* startsbuf; cudaGetSymbolAddress((void**)&startsbuf, g_starts);

    float* kpd = scratch + OFF_KPD;
    float* vpd = scratch + OFF_VPD;
    float* kpe = scratch + OFF_KPE;
    float* vpe = scratch + OFF_VPE;
    float* lat = scratch + OFF_LAT;
    float* nl  = scratch + OFF_NL;
    float* tmp = scratch + OFF_TMP;
    float* qh  = scratch + OFF_QH;
    float* ob  = scratch + OFF_O;
    float* h1  = scratch + OFF_H1;
    float* hh  = scratch + OFF_HH;
    int* starts_d = startsbuf;
    int* starts_e = startsbuf + (BB + 1);

    starts_kernel<<<1, BB>>>(drug_batch, NDRUG, starts_d);
    starts_kernel<<<1, BB>>>(enzyme_batch, NENZ, starts_e);
    init_lat_kernel<<<(BB * NL * DD) / 256, 256>>>(latents, lat);

    const int MROW = BB * NL;  // 8192

    for (int l = 0; l < LAYERS; l++) {
        const float* Wd = mha_d_w + (size_t)l * 3 * DD * DD;
        const float* Bd = mha_d_b + (size_t)l * 3 * DD;
        const float* We = mha_e_w + (size_t)l * 3 * DD * DD;
        const float* Be = mha_e_b + (size_t)l * 3 * DD;

        ln_kernel<<<MROW, DD>>>(lat, ln1_g + l * DD, ln1_b + l * DD, nl);

        // --- drug branch ---
        run_gemm(nl, wq_d + (size_t)l * DD * DD, bq_d + l * DD, tmp, MROW, DD, DD, 0);
        run_gemm(tmp, Wd, Bd, qh, MROW, DD, DD, 0);
        run_gemm(drug_k, Wd + DD * DD,     Bd + DD,     kpd, NDRUG, DD, DD, 0);
        run_gemm(drug_v, Wd + 2 * DD * DD, Bd + 2 * DD, vpd, NDRUG, DD, DD, 0);
        attn_kernel<<<dim3(BB, NHEAD), 128, (512 + 16 * CAP_D) * sizeof(float)>>>(
            qh, kpd, vpd, starts_d, Bd + 2 * DD, ob, CAP_D);
        run_gemm(ob, mha_d_ow + (size_t)l * DD * DD, mha_d_ob + l * DD, lat, MROW, DD, DD, 2);

        // --- enzyme branch ---
        run_gemm(nl, wq_e + (size_t)l * DD * DD, bq_e + l * DD, tmp, MROW, DD, DD, 0);
        run_gemm(tmp, We, Be, qh, MROW, DD, DD, 0);
        run_gemm(enzyme_k, We + DD * DD,     Be + DD,     kpe, NENZ, DD, DD, 0);
        run_gemm(enzyme_v, We + 2 * DD * DD, Be + 2 * DD, vpe, NENZ, DD, DD, 0);
        attn_kernel<<<dim3(BB, NHEAD), 128, (512 + 16 * CAP_E) * sizeof(float)>>>(
            qh, kpe, vpe, starts_e, Be + 2 * DD, ob, CAP_E);
        run_gemm(ob, mha_e_ow + (size_t)l * DD * DD, mha_e_ob + l * DD, lat, MROW, DD, DD, 2);

        // --- FFN ---
        ln_kernel<<<MROW, DD>>>(lat, ln2_g + l * DD, ln2_b + l * DD, nl);
        run_gemm(nl, ffn_w1 + (size_t)l * 2 * DD * DD, ffn_b1 + l * 2 * DD, h1, MROW, DD, 2 * DD, 1);
        run_gemm(h1, ffn_w2 + (size_t)l * DD * 2 * DD, ffn_b2 + l * DD, lat, MROW, 2 * DD, DD, 2);
    }

    // head: lat viewed as [512, 2048]
    run_gemm(lat, head_w1, head_b1, hh, BB, NL * DD, DD, 1);
    head2_kernel<<<BB, DD>>>(hh, head_w2, head_b2, (float*)d_out);
}